// round 10
// baseline (speedup 1.0000x reference)
#include <cuda_runtime.h>
#include <cuda_bf16.h>
#include <cfloat>

// Problem constants (S=4096 tokens, D=1024 dim, E=64 experts)
constexpr int S   = 4096;
constexpr int D   = 1024;
constexpr int E   = 64;
constexpr int CAP = 512;          // 2 * ceil(S / (E/4))
constexpr int KSLICES = 4;        // split-K factor (K-slice = 256)
constexpr int KS      = D / KSLICES;
constexpr int NGATE   = S / 8;    // gate blocks (8 tokens each)
constexpr int ROW     = E * CAP;  // 32768 floats per token per tensor
// out layout (float32): [0] = l_aux, [1 .. 1+S*E*CAP) = combine, then dispatch

// ---------------- scratch (device globals; no allocation allowed) ----------
__device__ float g_part[2 * KSLICES * S * E];    // split-K partial logits (8MB)
__device__ int   g_expert[S];
__device__ float g_gate[S];
__device__ int   g_loc[S];
__device__ float g_me_part[NGATE * E];           // per-gate-block me partials
__device__ float g_laux;

// ---------------- split-K GEMM: partial logits = X @ W^T -------------------
// grid (64 tok-tiles, 2 gemms, 4 K-slices). Tile 64x64, K-chunks of 64.
__global__ __launch_bounds__(256) void gemm_kernel(
    const float* __restrict__ A1, const float* __restrict__ A2,
    const float* __restrict__ W1, const float* __restrict__ W2)
{
    const float* A = blockIdx.y ? A2 : A1;
    const float* W = blockIdx.y ? W2 : W1;
    float* out = g_part + ((size_t)(blockIdx.y * KSLICES + blockIdx.z)) * S * E;
    const int tok0 = blockIdx.x * 64;
    const int kt0  = blockIdx.z * KS;

    __shared__ float As[64 * 64];
    __shared__ float Ws[64 * 64];

    const int tid = threadIdx.x;
    const int lr  = tid >> 4;   // loader row base (0..15)
    const int lc  = tid & 15;   // loader float4 column (0..15)
    const int tr  = tid & 15;   // compute: token quad
    const int ec  = tid >> 4;   // compute: expert quad

    float acc[4][4];
#pragma unroll
    for (int i = 0; i < 4; i++)
#pragma unroll
        for (int j = 0; j < 4; j++) acc[i][j] = 0.0f;

    float4 pa[4], pw[4];
#pragma unroll
    for (int p = 0; p < 4; p++) {
        int row = lr + p * 16;
        pa[p] = *(const float4*)&A[(size_t)(tok0 + row) * D + kt0 + lc * 4];
        pw[p] = *(const float4*)&W[(size_t)row * D + kt0 + lc * 4];
    }

    for (int kt = kt0; kt < kt0 + KS; kt += 64) {
#pragma unroll
        for (int p = 0; p < 4; p++) {
            int row = lr + p * 16;
            int sc  = (lc ^ ((row >> 2) & 7)) * 4;
            *(float4*)&As[row * 64 + sc] = pa[p];
            *(float4*)&Ws[row * 64 + sc] = pw[p];
        }
        __syncthreads();

        if (kt + 64 < kt0 + KS) {
#pragma unroll
            for (int p = 0; p < 4; p++) {
                int row = lr + p * 16;
                pa[p] = *(const float4*)&A[(size_t)(tok0 + row) * D + kt + 64 + lc * 4];
                pw[p] = *(const float4*)&W[(size_t)row * D + kt + 64 + lc * 4];
            }
        }

#pragma unroll
        for (int kk = 0; kk < 16; kk++) {
            float4 av[4], wv[4];
#pragma unroll
            for (int i = 0; i < 4; i++) {
                int tok = tr * 4 + i;
                av[i] = *(const float4*)&As[tok * 64 + ((kk ^ (tr & 7)) * 4)];
                int e = ec * 4 + i;
                wv[i] = *(const float4*)&Ws[e * 64 + ((kk ^ (ec & 7)) * 4)];
            }
#pragma unroll
            for (int i = 0; i < 4; i++)
#pragma unroll
                for (int j = 0; j < 4; j++) {
                    acc[i][j] += av[i].x * wv[j].x;
                    acc[i][j] += av[i].y * wv[j].y;
                    acc[i][j] += av[i].z * wv[j].z;
                    acc[i][j] += av[i].w * wv[j].w;
                }
        }
        __syncthreads();
    }

#pragma unroll
    for (int i = 0; i < 4; i++)
        *(float4*)&out[(size_t)(tok0 + tr * 4 + i) * E + ec * 4] =
            make_float4(acc[i][0], acc[i][1], acc[i][2], acc[i][3]);
}

// ---------------- gating: warp per token, sums split-K partials ------------
__global__ __launch_bounds__(256) void gate_kernel() {
    __shared__ float sMe[8 * 64];
    const int b    = blockIdx.x;
    const int tid  = threadIdx.x;
    const int lane = tid & 31;
    const int w    = tid >> 5;
    const int t    = b * 8 + w;

    float l1a = 0.f, l1b = 0.f, l2a = 0.f, l2b = 0.f;
#pragma unroll
    for (int kz = 0; kz < KSLICES; kz++) {
        const float* p1 = g_part + (size_t)kz * S * E + (size_t)t * E;
        const float* p2 = g_part + (size_t)(KSLICES + kz) * S * E + (size_t)t * E;
        l1a += p1[lane];  l1b += p1[32 + lane];
        l2a += p2[lane];  l2b += p2[32 + lane];
    }
    if (lane == 0) l1a = -1e9f;      // expert 0 excluded from group gating

    // ---- stage 1: top-16 of group logits (softmax monotone -> skip it)
    bool sela = false, selb = false;
#pragma unroll 1
    for (int it = 0; it < 16; it++) {
        float va = sela ? -FLT_MAX : l1a;
        float vb = selb ? -FLT_MAX : l1b;
        float v; int idx;
        if (vb > va) { v = vb; idx = lane + 32; } else { v = va; idx = lane; }
#pragma unroll
        for (int off = 16; off > 0; off >>= 1) {
            float ov = __shfl_xor_sync(0xffffffffu, v, off);
            int   oi = __shfl_xor_sync(0xffffffffu, idx, off);
            if (ov > v || (ov == v && oi < idx)) { v = ov; idx = oi; }
        }
        if (idx == lane) sela = true;
        else if (idx == lane + 32) selb = true;
    }

    // ---- stage 2: masked softmax over the 16 selected experts
    float va = sela ? l2a : -FLT_MAX;
    float vb = selb ? l2b : -FLT_MAX;
    float m; int ei;
    if (vb > va) { m = vb; ei = lane + 32; } else { m = va; ei = lane; }
#pragma unroll
    for (int off = 16; off > 0; off >>= 1) {
        float ov = __shfl_xor_sync(0xffffffffu, m, off);
        int   oi = __shfl_xor_sync(0xffffffffu, ei, off);
        if (ov > m || (ov == m && oi < ei)) { m = ov; ei = oi; }
    }

    float ea = sela ? expf(l2a - m) : 0.0f;
    float eb = selb ? expf(l2b - m) : 0.0f;
    float ssum = ea + eb;
#pragma unroll
    for (int off = 16; off > 0; off >>= 1)
        ssum += __shfl_xor_sync(0xffffffffu, ssum, off);
    float inv = 1.0f / ssum;

    if (lane == 0) { g_expert[t] = ei; g_gate[t] = inv; }

    sMe[w * 64 + lane]      = sela ? ea * inv : 0.0f;
    sMe[w * 64 + 32 + lane] = selb ? eb * inv : 0.0f;
    __syncthreads();
    if (tid < 64) {
        float s = 0.0f;
#pragma unroll
        for (int ww = 0; ww < 8; ww++) s += sMe[ww * 64 + tid];
        g_me_part[b * 64 + tid] = s;
    }
}

// ---------------- locations via match.any ballots + l_aux ------------------
__global__ __launch_bounds__(1024) void loc_kernel() {
    __shared__ int   sCnt[128][E];     // per-window per-expert counts (32 KB)
    __shared__ float sPart[16][E];     // me reduction staging (4 KB)
    __shared__ float sMe[E];

    const int tid  = threadIdx.x;
    const int lane = tid & 31;
    const int wp   = tid >> 5;         // warp id 0..31

    for (int i = tid; i < 128 * E; i += 1024) ((int*)sCnt)[i] = 0;
    __syncthreads();

    int   eReg[4];
    unsigned mReg[4];
#pragma unroll
    for (int k = 0; k < 4; k++) {
        int win = wp + k * 32;
        int e   = g_expert[win * 32 + lane];
        unsigned mask = __match_any_sync(0xffffffffu, e);
        eReg[k] = e; mReg[k] = mask;
        if ((mask & ((1u << lane) - 1)) == 0)     // leader lane of group
            sCnt[win][e] = __popc(mask);
    }

    {   // me partial reduction
        int e = tid & 63, i = tid >> 6;
        float s = 0.0f;
        for (int b = i * 32; b < (i + 1) * 32; b++) s += g_me_part[b * 64 + e];
        sPart[i][e] = s;
    }
    __syncthreads();

    if (tid < 64) {                    // exclusive window-scan; ce = total
        int run = 0;
#pragma unroll 4
        for (int win = 0; win < 128; win++) {
            int c = sCnt[win][tid];
            sCnt[win][tid] = run;
            run += c;
        }
        float me = 0.0f;
#pragma unroll
        for (int i = 0; i < 16; i++) me += sPart[i][tid];
        sMe[tid] = me * (float)run;
    }
    __syncthreads();

#pragma unroll
    for (int k = 0; k < 4; k++) {
        int win  = wp + k * 32;
        int rank = sCnt[win][eReg[k]] + __popc(mReg[k] & ((1u << lane) - 1));
        g_loc[win * 32 + lane] = rank;
    }

    if (tid == 0) {
        float sum = 0.0f;
        for (int ee = 0; ee < E; ee++) sum += sMe[ee];
        g_laux = sum * (1.0f / 65536.0f);   // sum(me*ce)/(S*S)/num_2nd*E*E
    }
}

// ---------------- fused fill + scatter -------------------------------------
// Block b < S: combine row of token b. Block S+b: dispatch row of token b.
// Each block streams its 128KB row of zeros, placing the single nonzero
// inline. Row base = out + 1 + half*S*ROW + s*ROW (addr ≡ 4 mod 16 ->
// 3-float scalar head, 8191 float4s, 1-float tail).
__global__ __launch_bounds__(256) void fill_scatter_kernel(float* __restrict__ out)
{
    const int b    = blockIdx.x;
    const int tid  = threadIdx.x;
    const int s    = b & (S - 1);
    const int half = b >> 12;                  // 0 = combine, 1 = dispatch

    if (b == 0 && tid == 0) out[0] = g_laux;

    const int loc = g_loc[s];
    const int tgt = (loc < CAP) ? g_expert[s] * CAP + loc : -1;
    const float val = half ? 1.0f : g_gate[s];

    float* base = out + 1 + (size_t)half * S * ROW + (size_t)s * ROW;

    // scalar head (row indices 0..2)
    if (tid < 3) base[tid] = (tid == tgt) ? val : 0.0f;
    // scalar tail (row index ROW-1)
    if (tid == 3) base[ROW - 1] = ((ROW - 1) == tgt) ? val : 0.0f;

    float4* p4 = (float4*)(base + 3);          // 16B-aligned
    const int n4 = (ROW - 4) / 4;              // 8191 float4s
    const int jt = (tgt >= 3) ? (tgt - 3) >> 2 : -1;
    const int ct = (tgt - 3) & 3;

    const float4 z = make_float4(0.f, 0.f, 0.f, 0.f);
#pragma unroll 4
    for (int j = tid; j < n4; j += 256) {
        float4 v = z;
        if (j == jt) ((float*)&v)[ct] = val;   // place the nonzero inline
        p4[j] = v;
    }
}

// ---------------- launch ----------------------------------------------------
extern "C" void kernel_launch(void* const* d_in, const int* in_sizes, int n_in,
                              void* d_out, int out_size) {
    const float* input1 = (const float*)d_in[0];
    const float* input2 = (const float*)d_in[1];
    const float* wg1    = (const float*)d_in[2];
    const float* wg2    = (const float*)d_in[3];
    float* out = (float*)d_out;

    dim3 g(S / 64, 2, KSLICES);
    gemm_kernel<<<g, 256>>>(input1, input2, wg1, wg2);
    gate_kernel<<<NGATE, 256>>>();
    loc_kernel<<<1, 1024>>>();
    fill_scatter_kernel<<<2 * S, 256>>>(out);
}

// round 12
// speedup vs baseline: 1.1231x; 1.1231x over previous
#include <cuda_runtime.h>
#include <cuda_bf16.h>
#include <cfloat>

// Problem constants (S=4096 tokens, D=1024 dim, E=64 experts)
constexpr int S   = 4096;
constexpr int D   = 1024;
constexpr int E   = 64;
constexpr int CAP = 512;          // 2 * ceil(S / (E/4))
constexpr int KSLICES = 4;        // split-K factor (K-slice = 256)
constexpr int KS      = D / KSLICES;
constexpr int NGATE   = S / 8;    // gate blocks (8 tokens each)
constexpr int ROW     = E * CAP;  // 32768 floats per token per tensor
// out layout (float32): [0] = l_aux, [1 .. 1+S*E*CAP) = combine, then dispatch

// ---------------- scratch (device globals; no allocation allowed) ----------
__device__ float g_part[2 * KSLICES * S * E];    // split-K partial logits (8MB)
__device__ int   g_expert[S];
__device__ float g_gate[S];
__device__ int   g_loc[S];
__device__ float g_me_part[NGATE * E];           // per-gate-block me partials
__device__ float g_laux;

// ---------------- side stream + events (R2/R8-proven pattern) --------------
static cudaStream_t g_s1 = nullptr;
static cudaEvent_t  g_evFork = nullptr, g_evJoin = nullptr;
namespace {
struct StreamInit {
    StreamInit() {
        if (cudaStreamCreateWithFlags(&g_s1, cudaStreamNonBlocking) != cudaSuccess)
            g_s1 = nullptr;
        if (cudaEventCreateWithFlags(&g_evFork, cudaEventDisableTiming) != cudaSuccess)
            g_evFork = nullptr;
        if (cudaEventCreateWithFlags(&g_evJoin, cudaEventDisableTiming) != cudaSuccess)
            g_evJoin = nullptr;
    }
};
static StreamInit g_streamInit;
}

// ---------------- bulk zero fill (R10-measured 6.35+ TB/s structure) -------
// 8192 blocks x 256 threads; each block zeroes one contiguous 128 KB chunk
// with 32 iterations of stride-4KB float4 stores. Same shape as the R10
// fill_scatter kernel that hit 80% of DRAM spec, minus the data dependency.
constexpr int  ZF_BLOCKS = 2 * S;                 // 8192
constexpr long long ZF_CHUNK4 = 8192;             // float4s per block (128 KB)

__global__ __launch_bounds__(256) void zero_fill_kernel(
    float4* __restrict__ p4, long long n4,
    float* __restrict__ out, long long out_elems)
{
    const float4 z = make_float4(0.f, 0.f, 0.f, 0.f);
    long long base = (long long)blockIdx.x * ZF_CHUNK4;
#pragma unroll 4
    for (int j = threadIdx.x; j < (int)ZF_CHUNK4; j += 256) {
        long long i = base + j;
        if (i < n4) p4[i] = z;
    }
    if (blockIdx.x == 0) {            // scalar tail (out_size % 4 elements)
        long long t0 = n4 * 4;
        for (long long j = t0 + threadIdx.x; j < out_elems; j += 256)
            out[j] = 0.0f;
    }
}

// ---------------- split-K GEMM: partial logits = X @ W^T -------------------
// grid (64 tok-tiles, 2 gemms, 4 K-slices). Tile 64x64, K-chunks of 64.
__global__ __launch_bounds__(256) void gemm_kernel(
    const float* __restrict__ A1, const float* __restrict__ A2,
    const float* __restrict__ W1, const float* __restrict__ W2)
{
    const float* A = blockIdx.y ? A2 : A1;
    const float* W = blockIdx.y ? W2 : W1;
    float* out = g_part + ((size_t)(blockIdx.y * KSLICES + blockIdx.z)) * S * E;
    const int tok0 = blockIdx.x * 64;
    const int kt0  = blockIdx.z * KS;

    __shared__ float As[64 * 64];
    __shared__ float Ws[64 * 64];

    const int tid = threadIdx.x;
    const int lr  = tid >> 4;   // loader row base (0..15)
    const int lc  = tid & 15;   // loader float4 column (0..15)
    const int tr  = tid & 15;   // compute: token quad
    const int ec  = tid >> 4;   // compute: expert quad

    float acc[4][4];
#pragma unroll
    for (int i = 0; i < 4; i++)
#pragma unroll
        for (int j = 0; j < 4; j++) acc[i][j] = 0.0f;

    float4 pa[4], pw[4];
#pragma unroll
    for (int p = 0; p < 4; p++) {
        int row = lr + p * 16;
        pa[p] = *(const float4*)&A[(size_t)(tok0 + row) * D + kt0 + lc * 4];
        pw[p] = *(const float4*)&W[(size_t)row * D + kt0 + lc * 4];
    }

    for (int kt = kt0; kt < kt0 + KS; kt += 64) {
#pragma unroll
        for (int p = 0; p < 4; p++) {
            int row = lr + p * 16;
            int sc  = (lc ^ ((row >> 2) & 7)) * 4;
            *(float4*)&As[row * 64 + sc] = pa[p];
            *(float4*)&Ws[row * 64 + sc] = pw[p];
        }
        __syncthreads();

        if (kt + 64 < kt0 + KS) {
#pragma unroll
            for (int p = 0; p < 4; p++) {
                int row = lr + p * 16;
                pa[p] = *(const float4*)&A[(size_t)(tok0 + row) * D + kt + 64 + lc * 4];
                pw[p] = *(const float4*)&W[(size_t)row * D + kt + 64 + lc * 4];
            }
        }

#pragma unroll
        for (int kk = 0; kk < 16; kk++) {
            float4 av[4], wv[4];
#pragma unroll
            for (int i = 0; i < 4; i++) {
                int tok = tr * 4 + i;
                av[i] = *(const float4*)&As[tok * 64 + ((kk ^ (tr & 7)) * 4)];
                int e = ec * 4 + i;
                wv[i] = *(const float4*)&Ws[e * 64 + ((kk ^ (ec & 7)) * 4)];
            }
#pragma unroll
            for (int i = 0; i < 4; i++)
#pragma unroll
                for (int j = 0; j < 4; j++) {
                    acc[i][j] += av[i].x * wv[j].x;
                    acc[i][j] += av[i].y * wv[j].y;
                    acc[i][j] += av[i].z * wv[j].z;
                    acc[i][j] += av[i].w * wv[j].w;
                }
        }
        __syncthreads();
    }

#pragma unroll
    for (int i = 0; i < 4; i++)
        *(float4*)&out[(size_t)(tok0 + tr * 4 + i) * E + ec * 4] =
            make_float4(acc[i][0], acc[i][1], acc[i][2], acc[i][3]);
}

// ---------------- gating: warp per token, sums split-K partials ------------
__global__ __launch_bounds__(256) void gate_kernel() {
    __shared__ float sMe[8 * 64];
    const int b    = blockIdx.x;
    const int tid  = threadIdx.x;
    const int lane = tid & 31;
    const int w    = tid >> 5;
    const int t    = b * 8 + w;

    float l1a = 0.f, l1b = 0.f, l2a = 0.f, l2b = 0.f;
#pragma unroll
    for (int kz = 0; kz < KSLICES; kz++) {
        const float* p1 = g_part + (size_t)kz * S * E + (size_t)t * E;
        const float* p2 = g_part + (size_t)(KSLICES + kz) * S * E + (size_t)t * E;
        l1a += p1[lane];  l1b += p1[32 + lane];
        l2a += p2[lane];  l2b += p2[32 + lane];
    }
    if (lane == 0) l1a = -1e9f;      // expert 0 excluded from group gating

    // ---- stage 1: top-16 of group logits (softmax monotone -> skip it)
    bool sela = false, selb = false;
#pragma unroll 1
    for (int it = 0; it < 16; it++) {
        float va = sela ? -FLT_MAX : l1a;
        float vb = selb ? -FLT_MAX : l1b;
        float v; int idx;
        if (vb > va) { v = vb; idx = lane + 32; } else { v = va; idx = lane; }
#pragma unroll
        for (int off = 16; off > 0; off >>= 1) {
            float ov = __shfl_xor_sync(0xffffffffu, v, off);
            int   oi = __shfl_xor_sync(0xffffffffu, idx, off);
            if (ov > v || (ov == v && oi < idx)) { v = ov; idx = oi; }
        }
        if (idx == lane) sela = true;
        else if (idx == lane + 32) selb = true;
    }

    // ---- stage 2: masked softmax over the 16 selected experts
    float va = sela ? l2a : -FLT_MAX;
    float vb = selb ? l2b : -FLT_MAX;
    float m; int ei;
    if (vb > va) { m = vb; ei = lane + 32; } else { m = va; ei = lane; }
#pragma unroll
    for (int off = 16; off > 0; off >>= 1) {
        float ov = __shfl_xor_sync(0xffffffffu, m, off);
        int   oi = __shfl_xor_sync(0xffffffffu, ei, off);
        if (ov > m || (ov == m && oi < ei)) { m = ov; ei = oi; }
    }

    float ea = sela ? expf(l2a - m) : 0.0f;
    float eb = selb ? expf(l2b - m) : 0.0f;
    float ssum = ea + eb;
#pragma unroll
    for (int off = 16; off > 0; off >>= 1)
        ssum += __shfl_xor_sync(0xffffffffu, ssum, off);
    float inv = 1.0f / ssum;

    if (lane == 0) { g_expert[t] = ei; g_gate[t] = inv; }

    sMe[w * 64 + lane]      = sela ? ea * inv : 0.0f;
    sMe[w * 64 + 32 + lane] = selb ? eb * inv : 0.0f;
    __syncthreads();
    if (tid < 64) {
        float s = 0.0f;
#pragma unroll
        for (int ww = 0; ww < 8; ww++) s += sMe[ww * 64 + tid];
        g_me_part[b * 64 + tid] = s;
    }
}

// ---------------- locations via match.any ballots + l_aux ------------------
__global__ __launch_bounds__(1024) void loc_kernel() {
    __shared__ int   sCnt[128][E];     // per-window per-expert counts (32 KB)
    __shared__ float sPart[16][E];     // me reduction staging (4 KB)
    __shared__ float sMe[E];

    const int tid  = threadIdx.x;
    const int lane = tid & 31;
    const int wp   = tid >> 5;         // warp id 0..31

    for (int i = tid; i < 128 * E; i += 1024) ((int*)sCnt)[i] = 0;
    __syncthreads();

    int   eReg[4];
    unsigned mReg[4];
#pragma unroll
    for (int k = 0; k < 4; k++) {
        int win = wp + k * 32;
        int e   = g_expert[win * 32 + lane];
        unsigned mask = __match_any_sync(0xffffffffu, e);
        eReg[k] = e; mReg[k] = mask;
        if ((mask & ((1u << lane) - 1)) == 0)     // leader lane of group
            sCnt[win][e] = __popc(mask);
    }

    {   // me partial reduction
        int e = tid & 63, i = tid >> 6;
        float s = 0.0f;
        for (int b = i * 32; b < (i + 1) * 32; b++) s += g_me_part[b * 64 + e];
        sPart[i][e] = s;
    }
    __syncthreads();

    if (tid < 64) {                    // exclusive window-scan; ce = total
        int run = 0;
#pragma unroll 4
        for (int win = 0; win < 128; win++) {
            int c = sCnt[win][tid];
            sCnt[win][tid] = run;
            run += c;
        }
        float me = 0.0f;
#pragma unroll
        for (int i = 0; i < 16; i++) me += sPart[i][tid];
        sMe[tid] = me * (float)run;
    }
    __syncthreads();

#pragma unroll
    for (int k = 0; k < 4; k++) {
        int win  = wp + k * 32;
        int rank = sCnt[win][eReg[k]] + __popc(mReg[k] & ((1u << lane) - 1));
        g_loc[win * 32 + lane] = rank;
    }

    if (tid == 0) {
        float sum = 0.0f;
        for (int ee = 0; ee < E; ee++) sum += sMe[ee];
        g_laux = sum * (1.0f / 65536.0f);   // sum(me*ce)/(S*S)/num_2nd*E*E
    }
}

// ---------------- sparse scatter into combine/dispatch + l_aux -------------
__global__ void scatter_kernel(float* __restrict__ out) {
    int s = blockIdx.x * 256 + threadIdx.x;
    if (s == 0) out[0] = g_laux;
    if (s >= S) return;
    int loc = g_loc[s];
    if (loc >= CAP) return;            // dropped token: everything stays 0
    size_t off = ((size_t)s * E + g_expert[s]) * CAP + loc;
    out[1 + off] = g_gate[s];
    out[1 + (size_t)S * E * CAP + off] = 1.0f;
}

// ---------------- launch ----------------------------------------------------
extern "C" void kernel_launch(void* const* d_in, const int* in_sizes, int n_in,
                              void* d_out, int out_size) {
    const float* input1 = (const float*)d_in[0];
    const float* input2 = (const float*)d_in[1];
    const float* wg1    = (const float*)d_in[2];
    const float* wg2    = (const float*)d_in[3];
    float* out = (float*)d_out;

    const long long n4 = (long long)out_size / 4;
    dim3 g(S / 64, 2, KSLICES);
    const bool forked = (g_s1 && g_evFork && g_evJoin);

    if (forked) {
        // Fork: compute chain on side stream, concurrent with the zero fill.
        cudaEventRecord(g_evFork, 0);
        cudaStreamWaitEvent(g_s1, g_evFork, 0);

        gemm_kernel<<<g, 256, 0, g_s1>>>(input1, input2, wg1, wg2);
        gate_kernel<<<NGATE, 256, 0, g_s1>>>();
        loc_kernel<<<1, 1024, 0, g_s1>>>();
        cudaEventRecord(g_evJoin, g_s1);

        // Dominant cost: zero 1.07 GB with the R10-proven fill structure.
        zero_fill_kernel<<<ZF_BLOCKS, 256>>>((float4*)out, n4,
                                             out, (long long)out_size);

        // Join, then sparse scatter into the zeroed buffer.
        cudaStreamWaitEvent(0, g_evJoin, 0);
        scatter_kernel<<<(S + 255) / 256, 256>>>(out);
    } else {
        // Fallback: fully serial on the captured stream.
        zero_fill_kernel<<<ZF_BLOCKS, 256>>>((float4*)out, n4,
                                             out, (long long)out_size);
        gemm_kernel<<<g, 256>>>(input1, input2, wg1, wg2);
        gate_kernel<<<NGATE, 256>>>();
        loc_kernel<<<1, 1024>>>();
        scatter_kernel<<<(S + 255) / 256, 256>>>(out);
    }
}